// round 5
// baseline (speedup 1.0000x reference)
#include <cuda_runtime.h>
#include <cuda_bf16.h>

// Geometry
#define NZg   192
#define PLANEg (192*192)
#define VOLg  (192*192*192)

// Tiling
#define TY      12                 // y rows computed per block
#define ROWS_T  (TY + 2)           // +1 halo row each side = 14
#define RS      196                // padded row stride in floats (192 + 4, kills bank alignment)
#define PLF     (ROWS_T * RS)      // floats per (channel,buffer) plane = 2744
#define NBUF    5                  // 5-buffer ring -> single __syncthreads per plane
#define THREADS 576                // 48 z-float4 groups x 12 y rows
#define SEG     8                  // x planes computed per block
#define NSEG    (192 / SEG)        // 24
#define NYT     (192 / TY)         // 16
#define NPART   (NSEG * NYT * 2)   // 768 block partials
#define SMEM_FLOATS (3 * NBUF * PLF)       // 41160
#define SMEM_BYTES  (SMEM_FLOATS * 4)      // 164640 B (needs opt-in)
#define F4_PER_PLANE (3 * ROWS_T * 48)     // 2016 cp.async per plane (all 3 channels)
#define NVOX  14155776.0           // 2 * 192^3

__device__ float        g_partials[NPART];
__device__ unsigned int g_count;   // zero at load; last block resets each launch

__device__ __forceinline__ unsigned smem_u32(const void* p) {
    unsigned r;
    asm("{ .reg .u64 t; cvta.to.shared.u64 t, %1; cvt.u32.u64 %0, t; }" : "=r"(r) : "l"(p));
    return r;
}

__device__ __forceinline__ void cpasync16(unsigned dst, const float* src) {
    asm volatile("cp.async.cg.shared.global [%0], [%1], 16;\n" :: "r"(dst), "l"(src));
}

__device__ __forceinline__ float robustf(float x) {
    float ax = fabsf(x);
    return (ax <= 0.01f) ? 0.5f * x * x : 0.01f * (ax - 0.005f);
}

__device__ __forceinline__ float voxel_contrib(
    float ux, float uy, float uz,
    float vx, float vy, float vz,
    float wx, float wy, float wz)
{
    float exy = 0.5f * (uy + vx);
    float exz = 0.5f * (uz + wx);
    float eyz = 0.5f * (vz + wy);
    float tr  = ux + vy + wz;
    float rt  = robustf(tr);
    float rxx = robustf(ux), ryy = robustf(vy), rzz = robustf(wz);
    float rxy = robustf(exy), rxz = robustf(exz), ryz = robustf(eyz);
    float energy = 0.5f * rt * rt
                 + 0.5f * (rxx * rxx + ryy * ryy + rzz * rzz
                           + 2.0f * (rxy * rxy + rxz * rxz + ryz * ryz));
    // Exactly as written in the reference (NOT the textbook determinant).
    float jac = (1.0f + ux) * ((1.0f + vy) * (1.0f + wz) - vz * wy)
              - uy * (vx * (1.0f + wz) - vz * (1.0f + wx))
              + uz * (vx * wy - (1.0f + vy) * (1.0f + wx));
    return energy + 0.1f * fmaxf(-jac, 0.0f);
}

// Issue cp.async for one x-plane (all 3 channels, 14 rows incl. y-halo, full z).
__device__ __forceinline__ void load_plane(unsigned sbase, const float* __restrict__ df_b,
                                           int xp, int buf, int y0, int tid)
{
    #pragma unroll 1
    for (int i = tid; i < F4_PER_PLANE; i += THREADS) {
        int ch  = i / (ROWS_T * 48);
        int rem = i - ch * (ROWS_T * 48);
        int r   = rem / 48;
        int zq  = rem - r * 48;
        int gy  = y0 + r - 1;
        gy = max(0, min(191, gy));
        const float* src = df_b + (size_t)ch * VOLg + (size_t)xp * PLANEg
                                + (size_t)gy * NZg + 4 * zq;
        unsigned dst = sbase + 4u * (unsigned)((ch * NBUF + buf) * PLF + r * RS + 4 * zq);
        cpasync16(dst, src);
    }
}

__device__ __forceinline__ int b5(int x) { return (x + 5) % 5; }   // valid for x >= -1

__global__ __launch_bounds__(THREADS)
void elastic_fused(const float* __restrict__ df, float* __restrict__ out)
{
    extern __shared__ float S[];
    const unsigned sbase = smem_u32(S);

    const int tid = threadIdx.x;
    const int zq  = tid % 48;          // z float4 index (z0 = 4*zq)
    const int yy  = tid / 48;          // 0..11
    const int r   = yy + 1;            // smem row (halo at 0 and 13)

    const int xs = blockIdx.x * SEG;
    const int y0 = blockIdx.y * TY;
    const int b  = blockIdx.z;
    const float* df_b = df + (size_t)b * 3 * VOLg;

    const int y  = y0 + yy;
    const float sy = (y > 0 && y < 191) ? 0.5f : 1.0f;

    // ---- prime: planes xs-1 (clamped), xs, xs+1 as one cp.async group ----
    load_plane(sbase, df_b, max(xs - 1, 0), b5(xs - 1), y0, tid);
    load_plane(sbase, df_b, xs,             b5(xs),     y0, tid);
    load_plane(sbase, df_b, min(xs + 1, 191), b5(xs + 1), y0, tid);
    asm volatile("cp.async.commit_group;\n" ::: "memory");

    float acc = 0.0f;

    for (int x = xs; x < xs + SEG; ++x) {
        // prefetch plane x+2 (needed by compute at x+1)
        if (x < xs + SEG - 1)
            load_plane(sbase, df_b, min(x + 2, 191), b5(x + 2), y0, tid);
        asm volatile("cp.async.commit_group;\n" ::: "memory");
        asm volatile("cp.async.wait_group 1;\n" ::: "memory");   // all but newest done
        __syncthreads();                                         // planes <= x+1 visible

        const int bm = b5(x - 1), bc = b5(x), bp = b5(x + 1);
        const float sx = (x > 0 && x < 191) ? 0.5f : 1.0f;

        float4 GX[3], GY[3], GZ[3];
        #pragma unroll
        for (int ch = 0; ch < 3; ++ch) {
            const int ic = (ch * NBUF + bc) * PLF + r * RS + 4 * zq;
            const float4 c  = *(const float4*)&S[ic];
            const float4 ym = *(const float4*)&S[ic - RS];
            const float4 yp = *(const float4*)&S[ic + RS];
            const float4 xm = *(const float4*)&S[(ch * NBUF + bm) * PLF + r * RS + 4 * zq];
            const float4 xp = *(const float4*)&S[(ch * NBUF + bp) * PLF + r * RS + 4 * zq];
            const float zm = (zq > 0)  ? S[ic - 1] : c.x;
            const float zp = (zq < 47) ? S[ic + 4] : c.w;

            GX[ch].x = (xp.x - xm.x) * sx;  GX[ch].y = (xp.y - xm.y) * sx;
            GX[ch].z = (xp.z - xm.z) * sx;  GX[ch].w = (xp.w - xm.w) * sx;

            GY[ch].x = (yp.x - ym.x) * sy;  GY[ch].y = (yp.y - ym.y) * sy;
            GY[ch].z = (yp.z - ym.z) * sy;  GY[ch].w = (yp.w - ym.w) * sy;

            GZ[ch].x = (zq > 0)  ? (c.y - zm) * 0.5f : (c.y - c.x);
            GZ[ch].y = (c.z - c.x) * 0.5f;
            GZ[ch].z = (c.w - c.y) * 0.5f;
            GZ[ch].w = (zq < 47) ? (zp - c.z) * 0.5f : (c.w - c.z);
        }

        acc += voxel_contrib(GX[0].x, GY[0].x, GZ[0].x,
                             GX[1].x, GY[1].x, GZ[1].x,
                             GX[2].x, GY[2].x, GZ[2].x);
        acc += voxel_contrib(GX[0].y, GY[0].y, GZ[0].y,
                             GX[1].y, GY[1].y, GZ[1].y,
                             GX[2].y, GY[2].y, GZ[2].y);
        acc += voxel_contrib(GX[0].z, GY[0].z, GZ[0].z,
                             GX[1].z, GY[1].z, GZ[1].z,
                             GX[2].z, GY[2].z, GZ[2].z);
        acc += voxel_contrib(GX[0].w, GY[0].w, GZ[0].w,
                             GX[1].w, GY[1].w, GZ[1].w,
                             GX[2].w, GY[2].w, GZ[2].w);
    }

    asm volatile("cp.async.wait_group 0;\n" ::: "memory");   // drain before smem reuse

    // ---- block reduction: warp shuffle -> static shared -> warp 0 ----
    __shared__ float  swarp[32];
    __shared__ bool   s_last;
    __shared__ double sdw[32];

    const int lane = tid & 31;
    const int wid  = tid >> 5;            // 18 warps

    #pragma unroll
    for (int o = 16; o > 0; o >>= 1)
        acc += __shfl_xor_sync(0xffffffffu, acc, o);
    if (lane == 0) swarp[wid] = acc;
    __syncthreads();

    if (tid < 32) {
        float v = (tid < THREADS / 32) ? swarp[tid] : 0.0f;
        #pragma unroll
        for (int o = 16; o > 0; o >>= 1)
            v += __shfl_xor_sync(0xffffffffu, v, o);
        if (tid == 0) {
            const int bid = blockIdx.x + NSEG * (blockIdx.y + NYT * blockIdx.z);
            g_partials[bid] = v;
            __threadfence();
            unsigned old = atomicAdd(&g_count, 1u);
            s_last = (old == NPART - 1);
        }
    }
    __syncthreads();

    // ---- last block: deterministic final sum in double ----
    if (s_last) {
        double d = (double)__ldcg(&g_partials[tid]);
        if (tid < NPART - THREADS)                       // 768 partials, 576 threads
            d += (double)__ldcg(&g_partials[tid + THREADS]);
        #pragma unroll
        for (int o = 16; o > 0; o >>= 1)
            d += __shfl_xor_sync(0xffffffffu, d, o);
        if (lane == 0) sdw[wid] = d;
        __syncthreads();
        if (tid < 32) {
            double v = (tid < THREADS / 32) ? sdw[tid] : 0.0;
            #pragma unroll
            for (int o = 16; o > 0; o >>= 1)
                v += __shfl_xor_sync(0xffffffffu, v, o);
            if (tid == 0) {
                g_count = 0;                              // reset for graph replay
                out[0] = (float)(v / NVOX);
            }
        }
    }
}

extern "C" void kernel_launch(void* const* d_in, const int* in_sizes, int n_in,
                              void* d_out, int out_size) {
    const float* df = (const float*)d_in[0];
    // Not a stream operation — safe under graph capture; idempotent.
    cudaFuncSetAttribute(elastic_fused, cudaFuncAttributeMaxDynamicSharedMemorySize, SMEM_BYTES);
    dim3 grid(NSEG, NYT, 2);
    elastic_fused<<<grid, THREADS, SMEM_BYTES>>>(df, (float*)d_out);
}

// round 9
// speedup vs baseline: 2.2513x; 2.2513x over previous
#include <cuda_runtime.h>
#include <cuda_bf16.h>

#define NZg    192
#define PLANEg (192 * 192)
#define VOLg   (192 * 192 * 192)

#define TYB     8                    // y rows per block
#define THREADS (48 * TYB)           // 384
#define SEG     32                   // x planes marched per thread
#define NXSEG   (192 / SEG)          // 6
#define NYT     (192 / TYB)          // 24
#define NPART   (NYT * NXSEG * 2)    // 288 block partials
#define NVOX    14155776.0           // 2 * 192^3

__device__ float        g_partials[NPART];
__device__ unsigned int g_count;     // zero at load; last block resets each launch

__device__ __forceinline__ float4 ld4(const float* __restrict__ p) {
    return *reinterpret_cast<const float4*>(p);
}

__device__ __forceinline__ float robustf(float x) {
    float ax = fabsf(x);
    return (ax <= 0.01f) ? 0.5f * x * x : 0.01f * (ax - 0.005f);
}

__device__ __forceinline__ float voxel_contrib(
    float ux, float uy, float uz,
    float vx, float vy, float vz,
    float wx, float wy, float wz)
{
    float exy = 0.5f * (uy + vx);
    float exz = 0.5f * (uz + wx);
    float eyz = 0.5f * (vz + wy);
    float tr  = ux + vy + wz;
    float rt  = robustf(tr);
    float rxx = robustf(ux), ryy = robustf(vy), rzz = robustf(wz);
    float rxy = robustf(exy), rxz = robustf(exz), ryz = robustf(eyz);
    float energy = 0.5f * rt * rt
                 + 0.5f * (rxx * rxx + ryy * ryy + rzz * rzz
                           + 2.0f * (rxy * rxy + rxz * rxz + ryz * ryz));
    // Exactly as written in the reference (NOT the textbook determinant).
    float jac = (1.0f + ux) * ((1.0f + vy) * (1.0f + wz) - vz * wy)
              - uy * (vx * (1.0f + wz) - vz * (1.0f + wx))
              + uz * (vx * wy - (1.0f + vy) * (1.0f + wx));
    return energy + 0.1f * fmaxf(-jac, 0.0f);
}

__global__ __launch_bounds__(THREADS, 2)
void elastic_march(const float* __restrict__ df, float* __restrict__ out)
{
    const int tid = threadIdx.x;
    const int zq  = tid % 48;                 // z float4 group, z0 = 4*zq
    const int yy  = tid / 48;                 // 0..TYB-1
    const int y   = blockIdx.x * TYB + yy;    // 0..191
    const int xs  = blockIdx.y * SEG;
    const int b   = blockIdx.z;

    const float* __restrict__ base = df + (size_t)b * 3 * VOLg;
    const size_t off0 = (size_t)y * NZg + 4 * zq;       // within-plane offset
    const size_t offm = (size_t)max(y - 1, 0)   * NZg + 4 * zq;
    const size_t offp = (size_t)min(y + 1, 191) * NZg + 4 * zq;
    const float sy = (y > 0 && y < 191) ? 0.5f : 1.0f;

    // Rolling register planes: a = x-1, c = x (per channel)
    float4 a[3], c[3];
    {
        const size_t pm = (size_t)max(xs - 1, 0) * PLANEg;
        const size_t pc = (size_t)xs * PLANEg;
        #pragma unroll
        for (int ch = 0; ch < 3; ++ch) {
            const float* p = base + (size_t)ch * VOLg;
            a[ch] = ld4(p + pm + off0);
            c[ch] = ld4(p + pc + off0);
        }
    }

    float acc = 0.0f;

    #pragma unroll 4
    for (int x = xs; x < xs + SEG; ++x) {
        const size_t pcur = (size_t)x * PLANEg;
        const size_t pnxt = (size_t)min(x + 1, 191) * PLANEg;
        const float  sx   = (x > 0 && x < 191) ? 0.5f : 1.0f;

        // Issue all loads first for MLP. n = new plane (DRAM/L2);
        // ym/yp/z-halos are at plane x -> L1 hits (loaded last step by
        // neighboring threads of this block).
        float4 n[3], ym4[3], yp4[3];
        float  zmv[3], zpv[3];
        #pragma unroll
        for (int ch = 0; ch < 3; ++ch) {
            const float* p = base + (size_t)ch * VOLg;
            n[ch]   = ld4(p + pnxt + off0);
            ym4[ch] = ld4(p + pcur + offm);
            yp4[ch] = ld4(p + pcur + offp);
            zmv[ch] = (zq > 0)  ? p[pcur + off0 - 1] : 0.0f;
            zpv[ch] = (zq < 47) ? p[pcur + off0 + 4] : 0.0f;
        }

        float4 GX[3], GY[3], GZ[3];
        #pragma unroll
        for (int ch = 0; ch < 3; ++ch) {
            const float4 cc = c[ch];
            GX[ch].x = (n[ch].x - a[ch].x) * sx;
            GX[ch].y = (n[ch].y - a[ch].y) * sx;
            GX[ch].z = (n[ch].z - a[ch].z) * sx;
            GX[ch].w = (n[ch].w - a[ch].w) * sx;

            GY[ch].x = (yp4[ch].x - ym4[ch].x) * sy;
            GY[ch].y = (yp4[ch].y - ym4[ch].y) * sy;
            GY[ch].z = (yp4[ch].z - ym4[ch].z) * sy;
            GY[ch].w = (yp4[ch].w - ym4[ch].w) * sy;

            GZ[ch].x = (zq > 0)  ? (cc.y - zmv[ch]) * 0.5f : (cc.y - cc.x);
            GZ[ch].y = (cc.z - cc.x) * 0.5f;
            GZ[ch].z = (cc.w - cc.y) * 0.5f;
            GZ[ch].w = (zq < 47) ? (zpv[ch] - cc.z) * 0.5f : (cc.w - cc.z);

            a[ch] = cc;        // roll
            c[ch] = n[ch];
        }

        acc += voxel_contrib(GX[0].x, GY[0].x, GZ[0].x,
                             GX[1].x, GY[1].x, GZ[1].x,
                             GX[2].x, GY[2].x, GZ[2].x);
        acc += voxel_contrib(GX[0].y, GY[0].y, GZ[0].y,
                             GX[1].y, GY[1].y, GZ[1].y,
                             GX[2].y, GY[2].y, GZ[2].y);
        acc += voxel_contrib(GX[0].z, GY[0].z, GZ[0].z,
                             GX[1].z, GY[1].z, GZ[1].z,
                             GX[2].z, GY[2].z, GZ[2].z);
        acc += voxel_contrib(GX[0].w, GY[0].w, GZ[0].w,
                             GX[1].w, GY[1].w, GZ[1].w,
                             GX[2].w, GY[2].w, GZ[2].w);
    }

    // ---- block reduction: warp shuffle -> shared -> warp 0 ----
    __shared__ float  swarp[32];
    __shared__ bool   s_last;
    __shared__ double sdw[32];

    const int lane = tid & 31;
    const int wid  = tid >> 5;                 // 12 warps

    #pragma unroll
    for (int o = 16; o > 0; o >>= 1)
        acc += __shfl_xor_sync(0xffffffffu, acc, o);
    if (lane == 0) swarp[wid] = acc;
    __syncthreads();

    if (tid < 32) {
        float v = (tid < THREADS / 32) ? swarp[tid] : 0.0f;
        #pragma unroll
        for (int o = 16; o > 0; o >>= 1)
            v += __shfl_xor_sync(0xffffffffu, v, o);
        if (tid == 0) {
            const int bid = blockIdx.x + NYT * (blockIdx.y + NXSEG * blockIdx.z);
            g_partials[bid] = v;
            __threadfence();
            unsigned old = atomicAdd(&g_count, 1u);
            s_last = (old == NPART - 1);
        }
    }
    __syncthreads();

    // ---- last block: deterministic final sum in double ----
    if (s_last) {
        double d = (tid < NPART) ? (double)__ldcg(&g_partials[tid]) : 0.0;
        #pragma unroll
        for (int o = 16; o > 0; o >>= 1)
            d += __shfl_xor_sync(0xffffffffu, d, o);
        if (lane == 0) sdw[wid] = d;
        __syncthreads();
        if (tid < 32) {
            double v = (tid < THREADS / 32) ? sdw[tid] : 0.0;
            #pragma unroll
            for (int o = 16; o > 0; o >>= 1)
                v += __shfl_xor_sync(0xffffffffu, v, o);
            if (tid == 0) {
                g_count = 0;                   // reset for graph replay
                out[0] = (float)(v / NVOX);
            }
        }
    }
}

extern "C" void kernel_launch(void* const* d_in, const int* in_sizes, int n_in,
                              void* d_out, int out_size) {
    const float* df = (const float*)d_in[0];
    dim3 grid(NYT, NXSEG, 2);   // 24 x 6 x 2 = 288 blocks, ~2/SM, one wave
    elastic_march<<<grid, THREADS>>>(df, (float*)d_out);
}